// round 1
// baseline (speedup 1.0000x reference)
#include <cuda_runtime.h>
#include <cstdint>

// Problem constants (fixed by the reference):
//   B=64, I=1024, O=1024, et in {0,1,2}
//   tnorm (op==0): val = (et==2 ? 1-x : x) + (et==0 ? +10 : 0), reduce = min
//   tconorm:       val = (et==2 ? 1-x : x) + (et==0 ? -10 : 0), reduce = max

#define B_DIM 64
#define I_DIM 1024
#define O_DIM 1024
#define WARPS_PER_BLOCK 16
#define THREADS (WARPS_PER_BLOCK * 32)

__global__ void __launch_bounds__(THREADS, 2)
ffcl_kernel(const float* __restrict__ x,
            const int4* __restrict__ et4,       // edge_type_idx viewed as int4
            const int* __restrict__ op_idx,
            float* __restrict__ out)
{
    __shared__ float xs[I_DIM];

    // blockIdx.x = b * (O_DIM/WARPS_PER_BLOCK) + o_group
    const int b  = blockIdx.x >> 6;          // O_DIM/WARPS_PER_BLOCK = 64 groups per b
    const int og = blockIdx.x & 63;

    // Stage x[b, :] into shared (4 KB)
    {
        const float4* xrow = reinterpret_cast<const float4*>(x + (size_t)b * I_DIM);
        float4* xs4 = reinterpret_cast<float4*>(xs);
        #pragma unroll
        for (int i = threadIdx.x; i < I_DIM / 4; i += THREADS)
            xs4[i] = xrow[i];
    }
    __syncthreads();

    const int warp = threadIdx.x >> 5;
    const int lane = threadIdx.x & 31;
    const int o    = og * WARPS_PER_BLOCK + warp;

    const bool tnorm = (op_idx[o] == 0);
    const float offset = tnorm ? 10.0f : -10.0f;

    // et row for (b, o): 1024 ints = 256 int4
    const int4* row = et4 + ((size_t)(b * O_DIM + o) * I_DIM) / 4;
    const float4* xs4 = reinterpret_cast<const float4*>(xs);

    // Each lane: 8 independent int4 loads (MLP=8), matching float4 from smem.
    int4   e[8];
    float4 xv[8];
    #pragma unroll
    for (int j = 0; j < 8; ++j) {
        const int idx4 = j * 32 + lane;       // coalesced across the warp
        e[j]  = __ldcs(row + idx4);           // streaming: read-once data
        xv[j] = xs4[idx4];
    }

    float red = tnorm ? INFINITY : -INFINITY;

    #pragma unroll
    for (int j = 0; j < 8; ++j) {
        // component-wise: v = (et==2 ? 1-x : x) + (et==0 ? offset : 0)
        float v0 = (e[j].x == 2) ? (1.0f - xv[j].x) : xv[j].x;
        float v1 = (e[j].y == 2) ? (1.0f - xv[j].y) : xv[j].y;
        float v2 = (e[j].z == 2) ? (1.0f - xv[j].z) : xv[j].z;
        float v3 = (e[j].w == 2) ? (1.0f - xv[j].w) : xv[j].w;
        if (e[j].x == 0) v0 += offset;
        if (e[j].y == 0) v1 += offset;
        if (e[j].z == 0) v2 += offset;
        if (e[j].w == 0) v3 += offset;
        if (tnorm) {
            red = fminf(red, fminf(fminf(v0, v1), fminf(v2, v3)));
        } else {
            red = fmaxf(red, fmaxf(fmaxf(v0, v1), fmaxf(v2, v3)));
        }
    }

    // Warp butterfly reduction
    if (tnorm) {
        #pragma unroll
        for (int s = 16; s > 0; s >>= 1)
            red = fminf(red, __shfl_xor_sync(0xffffffffu, red, s));
    } else {
        #pragma unroll
        for (int s = 16; s > 0; s >>= 1)
            red = fmaxf(red, __shfl_xor_sync(0xffffffffu, red, s));
    }

    if (lane == 0)
        out[(size_t)b * O_DIM + o] = red;
}

extern "C" void kernel_launch(void* const* d_in, const int* in_sizes, int n_in,
                              void* d_out, int out_size)
{
    (void)in_sizes; (void)n_in; (void)out_size;
    const float* x      = (const float*)d_in[0];
    const int4*  et4    = (const int4*)d_in[1];
    const int*   op_idx = (const int*)d_in[2];
    float*       out    = (float*)d_out;

    const int blocks = B_DIM * (O_DIM / WARPS_PER_BLOCK);  // 4096
    ffcl_kernel<<<blocks, THREADS>>>(x, et4, op_idx, out);
}